// round 4
// baseline (speedup 1.0000x reference)
#include <cuda_runtime.h>
#include <cstdint>

// Problem constants
#define BB      2
#define CC      384
#define DD      32
#define HH      32
#define WW      32
#define HEADS   12
#define HD      32
#define WS      5
#define PADW    2
#define SSP     (DD*HH*WW)          // 32768 spatial
#define SCALE   0.17677669529663687f // 32^-0.5

// Scratch (device globals; allocation inside kernel_launch is forbidden)
__device__ float g_qkv[(size_t)BB * 3 * CC * SSP];   // [b][o(1152)][s]
__device__ float g_attn[(size_t)BB * CC * SSP];      // [b][c][s]

// ---------------------------------------------------------------------------
// SGEMM: C[b][m][n] = sum_k A[m][k] * B[b][k][n] + bias[m]
// BM=64, BN=64, BK=16, 256 threads, 4x4 microtile. All dims divide evenly.
// ---------------------------------------------------------------------------
__global__ __launch_bounds__(256)
void sgemm_bias_kernel(const float* __restrict__ A,
                       const float* __restrict__ B,
                       const float* __restrict__ bias,
                       float* __restrict__ C,
                       int M, int N, int K,
                       size_t strideB, size_t strideC)
{
    __shared__ __align__(16) float As[16][64];
    __shared__ __align__(16) float Bs[16][64];

    const float* Bp = B + (size_t)blockIdx.z * strideB;
    float*       Cp = C + (size_t)blockIdx.z * strideC;

    const int tid = threadIdx.x;
    const int tx  = tid & 15;        // n
    const int ty  = tid >> 4;        // m
    const int m0  = blockIdx.y * 64;
    const int n0  = blockIdx.x * 64;

    // A-tile load map: 64 rows x 16 k, one float4 per thread along K
    const int aRow = tid >> 2;
    const int aCol = (tid & 3) * 4;
    // B-tile load map: 16 k-rows x 64 n, one float4 per thread along N
    const int bRow = tid >> 4;
    const int bCol = (tid & 15) * 4;

    float acc[4][4];
#pragma unroll
    for (int i = 0; i < 4; i++)
#pragma unroll
        for (int j = 0; j < 4; j++) acc[i][j] = 0.f;

    for (int k0 = 0; k0 < K; k0 += 16) {
        float4 av = *(const float4*)(A + (size_t)(m0 + aRow) * K + k0 + aCol);
        As[aCol + 0][aRow] = av.x;
        As[aCol + 1][aRow] = av.y;
        As[aCol + 2][aRow] = av.z;
        As[aCol + 3][aRow] = av.w;
        float4 bv = *(const float4*)(Bp + (size_t)(k0 + bRow) * N + n0 + bCol);
        *(float4*)&Bs[bRow][bCol] = bv;
        __syncthreads();

#pragma unroll
        for (int kk = 0; kk < 16; kk++) {
            float a[4], b[4];
            *(float4*)a = *(const float4*)&As[kk][ty * 4];
            *(float4*)b = *(const float4*)&Bs[kk][tx * 4];
#pragma unroll
            for (int i = 0; i < 4; i++)
#pragma unroll
                for (int j = 0; j < 4; j++)
                    acc[i][j] = fmaf(a[i], b[j], acc[i][j]);
        }
        __syncthreads();
    }

#pragma unroll
    for (int i = 0; i < 4; i++) {
        float bv = bias[m0 + ty * 4 + i];
        float4 o;
        o.x = acc[i][0] + bv;
        o.y = acc[i][1] + bv;
        o.z = acc[i][2] + bv;
        o.w = acc[i][3] + bv;
        *(float4*)(Cp + (size_t)(m0 + ty * 4 + i) * N + n0 + tx * 4) = o;
    }
}

// ---------------------------------------------------------------------------
// Fused windowed attention with online softmax.
// Grid: (D, H/4, B*HEADS).  Block: 128 threads = 32(x) * 4(y).
// Per dz: stage k,v z-slice tile [32ch][8y][36x] (zero-filled halo) in smem.
// pos_embed [32][125] staged once in smem.
// ---------------------------------------------------------------------------
#define TY       4
#define XH       36                  // 32 + 2*PAD
#define YH       (TY + 2*PADW)       // 8
#define SLICE_EL (HD * YH * XH)      // 9216
#define PE_EL    (HD * WS * WS * WS) // 4000
#define ATTN_SMEM_BYTES ((2 * SLICE_EL + PE_EL) * 4)  // 89728

__global__ __launch_bounds__(128)
void attn3d_kernel(const float* __restrict__ qkv,
                   const float* __restrict__ pos_embed,
                   float* __restrict__ attn_out)
{
    extern __shared__ float smem[];
    float* ksm = smem;                 // [HD][YH][XH]
    float* vsm = smem + SLICE_EL;
    float* pes = smem + 2 * SLICE_EL;  // [HD][125]

    const int tid  = threadIdx.x;
    const int tx   = tid & 31;
    const int ty   = tid >> 5;
    const int z    = blockIdx.x;
    const int y0   = blockIdx.y * TY;
    const int bh   = blockIdx.z;
    const int b    = bh / HEADS;
    const int head = bh % HEADS;

    const int y = y0 + ty;
    const int x = tx;

    const float* qbase = qkv + ((size_t)b * (3 * CC) + head * HD) * SSP;
    const float* kbase = qbase + (size_t)CC * SSP;
    const float* vbase = qbase + (size_t)(2 * CC) * SSP;

    // Stage pos_embed
    for (int i = tid; i < PE_EL; i += 128) pes[i] = pos_embed[i];

    // Load q into registers
    const size_t svox = (size_t)z * (HH * WW) + y * WW + x;
    float qreg[HD];
#pragma unroll
    for (int hd = 0; hd < HD; hd++) qreg[hd] = qbase[(size_t)hd * SSP + svox];

    float m = -1e30f;
    float l = 0.f;
    float out[HD];
#pragma unroll
    for (int hd = 0; hd < HD; hd++) out[hd] = 0.f;

    for (int dz = 0; dz < WS; dz++) {
        const int zs = z + dz - PADW;
        const bool zin = (zs >= 0) && (zs < DD);
        // Stage k/v slice (zero padded)
        for (int idx = tid; idx < SLICE_EL; idx += 128) {
            const int ch = idx / (YH * XH);
            const int r  = idx - ch * (YH * XH);
            const int yy = r / XH;
            const int xx = r - yy * XH;
            const int ys = y0 + yy - PADW;
            const int xs = xx - PADW;
            float kv = 0.f, vv = 0.f;
            if (zin && ys >= 0 && ys < HH && xs >= 0 && xs < WW) {
                const size_t g = (size_t)ch * SSP + (size_t)zs * (HH * WW) + ys * WW + xs;
                kv = kbase[g];
                vv = vbase[g];
            }
            ksm[idx] = kv;
            vsm[idx] = vv;
        }
        __syncthreads();

        for (int dy = 0; dy < WS; dy++) {
            for (int dx = 0; dx < WS; dx++) {
                const int off  = (dz * WS + dy) * WS + dx;
                const int sidx = (ty + dy) * XH + tx + dx;
                float s = 0.f;
#pragma unroll
                for (int hd = 0; hd < HD; hd++)
                    s = fmaf(qreg[hd], ksm[hd * (YH * XH) + sidx] + pes[hd * 125 + off], s);
                s *= SCALE;

                if (s > m) {
                    const float c = __expf(m - s);
                    m = s;
                    l = l * c + 1.f;
#pragma unroll
                    for (int hd = 0; hd < HD; hd++)
                        out[hd] = out[hd] * c + vsm[hd * (YH * XH) + sidx];
                } else {
                    const float p = __expf(s - m);
                    l += p;
#pragma unroll
                    for (int hd = 0; hd < HD; hd++)
                        out[hd] = fmaf(p, vsm[hd * (YH * XH) + sidx], out[hd]);
                }
            }
        }
        __syncthreads();
    }

    const float inv = 1.f / l;
    float* obase = attn_out + ((size_t)b * CC + head * HD) * SSP + svox;
#pragma unroll
    for (int hd = 0; hd < HD; hd++) obase[(size_t)hd * SSP] = out[hd] * inv;
}

// ---------------------------------------------------------------------------
// Launch
// ---------------------------------------------------------------------------
extern "C" void kernel_launch(void* const* d_in, const int* in_sizes, int n_in,
                              void* d_out, int out_size)
{
    const float* x         = (const float*)d_in[0];
    const float* w_qkv     = (const float*)d_in[1];
    const float* b_qkv     = (const float*)d_in[2];
    const float* w_proj    = (const float*)d_in[3];
    const float* b_proj    = (const float*)d_in[4];
    const float* pos_embed = (const float*)d_in[5];
    float* outp = (float*)d_out;

    float* qkv;  cudaGetSymbolAddress((void**)&qkv,  g_qkv);
    float* attn; cudaGetSymbolAddress((void**)&attn, g_attn);

    // 1) QKV projection: M=1152, N=32768, K=384, batched over b=2
    {
        dim3 grid(SSP / 64, (3 * CC) / 64, BB);
        sgemm_bias_kernel<<<grid, 256>>>(w_qkv, x, b_qkv, qkv,
                                         3 * CC, SSP, CC,
                                         (size_t)CC * SSP,
                                         (size_t)(3 * CC) * SSP);
    }

    // 2) Fused windowed attention
    {
        cudaFuncSetAttribute(attn3d_kernel,
                             cudaFuncAttributeMaxDynamicSharedMemorySize,
                             ATTN_SMEM_BYTES);
        dim3 grid(DD, HH / TY, BB * HEADS);
        attn3d_kernel<<<grid, 128, ATTN_SMEM_BYTES>>>(qkv, pos_embed, attn);
    }

    // 3) Output projection: M=384, N=32768, K=384
    {
        dim3 grid(SSP / 64, CC / 64, BB);
        sgemm_bias_kernel<<<grid, 256>>>(w_proj, attn, b_proj, outp,
                                         CC, SSP, CC,
                                         (size_t)CC * SSP,
                                         (size_t)CC * SSP);
    }
}